// round 1
// baseline (speedup 1.0000x reference)
#include <cuda_runtime.h>
#include <math.h>

// ConvLSTM, 16 sequential fused conv+LSTM steps.
// x: (8,16,64,64,64) f32, Wk: (256,128,3,3) f32
// out: [hid (8*64*64*64) | cell (8*64*64*64)] f32
//
// Block: 16x16 spatial tile of one batch image, 64 out-channels =
//        {gate i,f,o,g} x 16 hidden channels (hd base = ocg*16).
// Thread: 4 consecutive x positions x (4 gates x 4 hidden ch) = 64 fp32 acc.
// LSTM pointwise fused in epilogue; cell kept in-place in d_out 2nd half;
// h double-buffered in device globals; final h -> d_out 1st half at t=15.

#define TILE 16
#define ICC  8   // input channels per smem chunk

__device__ float g_hbuf[2][8u * 64u * 64u * 64u];

__global__ __launch_bounds__(256, 2)
void convlstm_step(const float* __restrict__ x,
                   const float* __restrict__ Wk,
                   float* __restrict__ hid_out,
                   float* __restrict__ cell_io,
                   int t, int last)
{
    __shared__ float in_s[ICC][18][19];   // input tile + halo, padded row
    __shared__ float w_s[64][76];         // [oc_local][r], r = ic*9+ky*3+kx (72 used)

    const int tid = threadIdx.x;
    const int og  = tid >> 6;        // 0..3 : which 4-hidden-ch subgroup
    const int sg  = tid & 63;        // 0..63: spatial group (4 x-positions)
    const int row = sg >> 2;         // 0..15 within tile
    const int col = (sg & 3) << 2;   // 0,4,8,12

    const int ty  = blockIdx.x >> 2; // tile row 0..3
    const int tx  = blockIdx.x & 3;  // tile col 0..3
    const int ocg = blockIdx.y;      // hidden-channel group 0..3 (16 each)
    const int b   = blockIdx.z;      // batch

    const float* h_in = g_hbuf[t & 1];
    float* h_out = last ? hid_out : g_hbuf[(t + 1) & 1];

    float acc[4][16];
#pragma unroll
    for (int p = 0; p < 4; p++)
#pragma unroll
        for (int q = 0; q < 16; q++) acc[p][q] = 0.f;

    const int nic = (t == 0) ? 64 : 128;   // t=0: h==0, skip h half

    for (int ic0 = 0; ic0 < nic; ic0 += ICC) {
        __syncthreads();
        const float* src = (ic0 < 64)
            ? x + (((size_t)b * 16 + t) * 64 + ic0) * 4096
            : h_in + ((size_t)b * 64 + (ic0 - 64)) * 4096;

        // stage input tile (with halo, zero-padded at image edges)
        for (int i = tid; i < ICC * 18 * 18; i += 256) {
            int ic  = i / 324;
            int rem = i - ic * 324;
            int yy  = rem / 18;
            int xx  = rem - yy * 18;
            int gy  = ty * TILE - 1 + yy;
            int gx  = tx * TILE - 1 + xx;
            float v = 0.f;
            if ((unsigned)gy < 64u && (unsigned)gx < 64u)
                v = src[ic * 4096 + gy * 64 + gx];
            in_s[ic][yy][xx] = v;
        }
        // stage weights: coalesced global (72 contiguous floats per oc),
        // conflict-free STS, broadcast LDS on the read side
        for (int i = tid; i < 64 * 72; i += 256) {
            int ocl = i / 72;
            int r   = i - ocl * 72;
            int oc  = (ocl >> 4) * 64 + ocg * 16 + (ocl & 15);  // gate*64 + hc
            w_s[ocl][r] = Wk[(size_t)oc * 1152 + (size_t)ic0 * 9 + r];
        }
        __syncthreads();

#pragma unroll
        for (int ic = 0; ic < ICC; ic++) {
#pragma unroll
            for (int ky = 0; ky < 3; ky++) {
                float xv[6];
#pragma unroll
                for (int u = 0; u < 6; u++)
                    xv[u] = in_s[ic][row + ky][col + u];
#pragma unroll
                for (int kx = 0; kx < 3; kx++) {
                    const int r = ic * 9 + ky * 3 + kx;
#pragma unroll
                    for (int g = 0; g < 4; g++) {
#pragma unroll
                        for (int jj = 0; jj < 4; jj++) {
                            float w = w_s[g * 16 + og * 4 + jj][r];
#pragma unroll
                            for (int p = 0; p < 4; p++)
                                acc[p][g * 4 + jj] =
                                    fmaf(xv[kx + p], w, acc[p][g * 4 + jj]);
                        }
                    }
                }
            }
        }
    }

    // fused LSTM pointwise epilogue
    const int gy  = ty * TILE + row;
    const int gx0 = tx * TILE + col;
#pragma unroll
    for (int jj = 0; jj < 4; jj++) {
        const int hc = ocg * 16 + og * 4 + jj;
        const size_t base = (((size_t)b * 64 + hc) * 64 + gy) * 64 + gx0;
#pragma unroll
        for (int p = 0; p < 4; p++) {
            float iv = 1.f / (1.f + __expf(-acc[p][0 * 4 + jj]));
            float fv = 1.f / (1.f + __expf(-acc[p][1 * 4 + jj]));
            float ov = 1.f / (1.f + __expf(-acc[p][2 * 4 + jj]));
            float gv = tanhf(acc[p][3 * 4 + jj]);
            float cold = (t == 0) ? 0.f : cell_io[base + p];
            float cnew = fv * cold + iv * gv;
            cell_io[base + p] = cnew;
            h_out[base + p]   = ov * tanhf(cnew);
        }
    }
}

extern "C" void kernel_launch(void* const* d_in, const int* in_sizes, int n_in,
                              void* d_out, int out_size)
{
    const float* x  = (const float*)d_in[0];
    const float* Wk = (const float*)d_in[1];
    float* out  = (float*)d_out;
    float* hid  = out;                  // first half
    float* cell = out + out_size / 2;   // second half

    dim3 grid(16, 4, 8), blk(256);
    for (int t = 0; t < 16; t++)
        convlstm_step<<<grid, blk>>>(x, Wk, hid, cell, t, t == 15 ? 1 : 0);
}